// round 3
// baseline (speedup 1.0000x reference)
#include <cuda_runtime.h>
#include <cstdint>

#define MAXB 64

// ---------------- global accumulators (scratch; zeroed each launch) ----------
__device__ double g_ce_acc;
__device__ float  g_reg_acc[MAXB];
__device__ float  g_ldm_acc[MAXB];
__device__ int    g_npos_acc[MAXB];

__global__ void rf_init_kernel() {
    int t = threadIdx.x;
    if (t == 0) g_ce_acc = 0.0;
    if (t < MAXB) { g_reg_acc[t] = 0.f; g_ldm_acc[t] = 0.f; g_npos_acc[t] = 0; }
}

__device__ __forceinline__ float smooth_l1(float d) {
    float a = fabsf(d);
    return a < 1.f ? 0.5f * d * d : a - 0.5f;
}

// GT: compile-time G (0 => runtime). APT: anchors per thread.
template<int GT, int APT>
__global__ void __launch_bounds__(256) rf_main_kernel(
    const float* __restrict__ pred_cls,
    const float* __restrict__ pred_bbox,
    const float* __restrict__ pred_ldm,
    const float* __restrict__ anchors,
    const float* __restrict__ gt_boxes,
    const float* __restrict__ gt_ldm,
    int B, int A, int G_rt)
{
    constexpr int GMAX = (GT > 0) ? GT : 64;
    const int G = (GT > 0) ? GT : G_rt;

    __shared__ float4 sgb[GMAX];        // gt boxes
    __shared__ float  ssz[GMAX];        // gt areas
    __shared__ float  sgl[GMAX * 10];   // gt landmarks

    const int b   = blockIdx.y;
    const int tid = threadIdx.x;

    if (tid < G) {
        float4 gbx = *(const float4*)(gt_boxes + ((size_t)b * G + tid) * 4);
        sgb[tid] = gbx;
        ssz[tid] = (gbx.z - gbx.x) * (gbx.w - gbx.y);
    }
    for (int i = tid; i < G * 10; i += blockDim.x)
        sgl[i] = gt_ldm[(size_t)b * G * 10 + i];
    __syncthreads();

    const int a0 = blockIdx.x * (blockDim.x * APT) + tid;

    float ax0[APT], ay0[APT], ax1[APT], ay1[APT], sa[APT];
    float bi[APT], sb[APT];    // best inter, best (area_a + area_g)
    int   bg[APT];
    bool  valid[APT];

    #pragma unroll
    for (int k = 0; k < APT; ++k) {
        int a = a0 + k * blockDim.x;
        valid[k] = (a < A);
        float4 an = valid[k] ? *(const float4*)(anchors + (size_t)a * 4)
                             : make_float4(0.f, 0.f, 1.f, 1.f);
        ax0[k] = an.x; ay0[k] = an.y; ax1[k] = an.z; ay1[k] = an.w;
        sa[k]  = (an.z - an.x) * (an.w - an.y);
        const float4 g0 = sgb[0];
        float iw = fmaxf(fminf(ax1[k], g0.z) - fmaxf(ax0[k], g0.x), 0.f);
        float ih = fmaxf(fminf(ay1[k], g0.w) - fmaxf(ay0[k], g0.y), 0.f);
        bi[k] = iw * ih;
        sb[k] = sa[k] + ssz[0];
        bg[k] = 0;
    }

    // Division-free IoU argmax: iou_new > iou_best  <=>  in*sb > bi*s,
    // using union + inter = area_a + area_g = s (exact identity).
    #pragma unroll 4
    for (int g = 1; g < G; ++g) {
        const float4 gb = sgb[g];
        const float  sg = ssz[g];
        #pragma unroll
        for (int k = 0; k < APT; ++k) {
            float iw = fmaxf(fminf(ax1[k], gb.z) - fmaxf(ax0[k], gb.x), 0.f);
            float ih = fmaxf(fminf(ay1[k], gb.w) - fmaxf(ay0[k], gb.y), 0.f);
            float in = iw * ih;
            float s  = sa[k] + sg;
            if (in * sb[k] > bi[k] * s) { bi[k] = in; sb[k] = s; bg[k] = g; }
        }
    }

    float ce_sum = 0.f;
    #pragma unroll
    for (int k = 0; k < APT; ++k) {
        if (!valid[k]) continue;
        int    a    = a0 + k * blockDim.x;
        size_t base = (size_t)b * A + a;
        // iou >= 0.5  <=>  3*bi >= sb
        bool pos = (3.f * bi[k] >= sb[k]);

        // stable 2-class log-softmax CE
        float2 c  = *(const float2*)(pred_cls + base * 2);
        float  mx = fmaxf(c.x, c.y);
        float  lse = mx + log1pf(__expf(fminf(c.x, c.y) - mx));
        ce_sum += lse - (pos ? c.y : c.x);

        if (pos) {   // rare path: only now touch pred_bbox / pred_landmarks
            float aw = ax1[k] - ax0[k], ah = ay1[k] - ay0[k];
            float acx = ax0[k] + 0.5f * aw, acy = ay0[k] + 0.5f * ah;
            float4 gb = sgb[bg[k]];
            float gw = gb.z - gb.x, gh = gb.w - gb.y;
            float gcx = gb.x + 0.5f * gw, gcy = gb.y + 0.5f * gh;

            float4 pb = *(const float4*)(pred_bbox + base * 4);
            float r = smooth_l1(pb.x - (gcx - acx) / aw)
                    + smooth_l1(pb.y - (gcy - acy) / ah)
                    + smooth_l1(pb.z - logf(gw / aw))
                    + smooth_l1(pb.w - logf(gh / ah));

            float l = 0.f;
            const float* pl = pred_ldm + base * 10;
            const float* gl = sgl + bg[k] * 10;
            #pragma unroll
            for (int j = 0; j < 10; ++j) l += smooth_l1(pl[j] - gl[j]);

            atomicAdd(&g_reg_acc[b], r);
            atomicAdd(&g_ldm_acc[b], l);
            atomicAdd(&g_npos_acc[b], 1);
        }
    }

    // block reduction of CE -> one double atomic per block
    #pragma unroll
    for (int o = 16; o > 0; o >>= 1)
        ce_sum += __shfl_down_sync(0xffffffffu, ce_sum, o);
    __shared__ float wsum[8];
    int w = tid >> 5, lane = tid & 31;
    if (lane == 0) wsum[w] = ce_sum;
    __syncthreads();
    if (w == 0) {
        int nw = blockDim.x >> 5;
        float v = (lane < nw) ? wsum[lane] : 0.f;
        #pragma unroll
        for (int o = 4; o > 0; o >>= 1)
            v += __shfl_down_sync(0xffffffffu, v, o);
        if (lane == 0) atomicAdd(&g_ce_acc, (double)v);
    }
}

__global__ void rf_final_kernel(float* __restrict__ out, int B, int A) {
    if (threadIdx.x == 0 && blockIdx.x == 0) {
        float cls = (float)(g_ce_acc / ((double)A * (double)B));
        float reg = 0.f, ldm = 0.f;
        for (int b = 0; b < B; ++b) {
            int np = g_npos_acc[b];
            if (np > 0) {
                reg += g_reg_acc[b] / ((float)np * 4.0f);
                ldm += g_ldm_acc[b] / ((float)np * 10.0f);
            }
        }
        reg /= (float)B;
        ldm /= (float)B;
        out[0] = cls + reg + ldm;   // total
        out[1] = cls;
        out[2] = reg;
        out[3] = ldm;
    }
}

extern "C" void kernel_launch(void* const* d_in, const int* in_sizes, int n_in,
                              void* d_out, int out_size) {
    const float* pred_cls  = (const float*)d_in[0];
    const float* pred_bbox = (const float*)d_in[1];
    const float* pred_ldm  = (const float*)d_in[2];
    const float* anchors   = (const float*)d_in[3];
    const float* gt_boxes  = (const float*)d_in[4];
    const float* gt_ldm    = (const float*)d_in[5];
    float* out = (float*)d_out;

    const int A = in_sizes[3] / 4;
    const int B = (A > 0) ? in_sizes[0] / (2 * A) : 1;
    const int G = (B > 0) ? in_sizes[4] / (4 * B) : 1;

    rf_init_kernel<<<1, MAXB>>>();

    constexpr int APT = 4;
    const int threads = 256;
    dim3 grid((A + threads * APT - 1) / (threads * APT), B);

    if (G == 32)
        rf_main_kernel<32, APT><<<grid, threads>>>(
            pred_cls, pred_bbox, pred_ldm, anchors, gt_boxes, gt_ldm, B, A, G);
    else
        rf_main_kernel<0, APT><<<grid, threads>>>(
            pred_cls, pred_bbox, pred_ldm, anchors, gt_boxes, gt_ldm, B, A, G);

    rf_final_kernel<<<1, 32>>>(out, B, A);
}